// round 16
// baseline (speedup 1.0000x reference)
#include <cuda_runtime.h>
#include <cuda_bf16.h>
#include <cuda_fp16.h>
#include <cstdint>
#include <math.h>

// Problem constants
#define B_   2
#define T_   2048
#define C_   2048
#define NH   16
#define NKV  8
#define HD   128
#define KVD  (NKV*HD)          // 1024
#define QKV_DIM (C_ + 2*KVD)   // 4096
#define EPS_ 1.1920929e-07f
#define SCALE_ 0.08838834764831845f   // 1/sqrt(128)

// ---------------- scratch (static device globals; allocation-free) ----------
__device__ float g_qkv[(size_t)B_*T_*QKV_DIM];   // 64 MB
__device__ __half g_xhi[(size_t)B_*T_*C_];
__device__ __half g_xlo[(size_t)B_*T_*C_];
__device__ __half g_wahi[(size_t)QKV_DIM*C_];
__device__ __half g_wphi[(size_t)C_*C_];
__device__ __half g_yhi[(size_t)B_*T_*C_];
__device__ __half g_ylo[(size_t)B_*T_*C_];
__device__ __half g_qhi[(size_t)B_*NH*T_*HD];
__device__ __half g_qlo[(size_t)B_*NH*T_*HD];
__device__ __half g_khi[(size_t)B_*NKV*T_*HD];
__device__ __half g_vhi[(size_t)B_*NKV*T_*HD];

// ---------------------------------------------------------------------------
// helpers
// ---------------------------------------------------------------------------
__device__ __forceinline__ uint32_t smem_u32(const void* p) {
    uint32_t a;
    asm("{ .reg .u64 t; cvta.to.shared.u64 t, %1; cvt.u32.u64 %0, t; }" : "=r"(a) : "l"(p));
    return a;
}
__device__ __forceinline__ void cp_async16(uint32_t dst, const void* src) {
    asm volatile("cp.async.cg.shared.global [%0], [%1], 16;" :: "r"(dst), "l"(src));
}
__device__ __forceinline__ void cp_commit() { asm volatile("cp.async.commit_group;"); }
__device__ __forceinline__ void cp_wait1() { asm volatile("cp.async.wait_group 1;"); }
__device__ __forceinline__ void cp_wait0() { asm volatile("cp.async.wait_group 0;"); }
__device__ __forceinline__ void ldm_x4(uint32_t& r0, uint32_t& r1, uint32_t& r2, uint32_t& r3, uint32_t a) {
    asm volatile("ldmatrix.sync.aligned.m8n8.x4.shared.b16 {%0,%1,%2,%3}, [%4];"
                 : "=r"(r0), "=r"(r1), "=r"(r2), "=r"(r3) : "r"(a));
}
__device__ __forceinline__ void ldmt_x4(uint32_t& r0, uint32_t& r1, uint32_t& r2, uint32_t& r3, uint32_t a) {
    asm volatile("ldmatrix.sync.aligned.m8n8.x4.trans.shared.b16 {%0,%1,%2,%3}, [%4];"
                 : "=r"(r0), "=r"(r1), "=r"(r2), "=r"(r3) : "r"(a));
}
__device__ __forceinline__ void mma_f16(float* d, const uint32_t* a, const uint32_t* b) {
    asm volatile(
        "mma.sync.aligned.m16n8k16.row.col.f32.f16.f16.f32 "
        "{%0,%1,%2,%3}, {%4,%5,%6,%7}, {%8,%9}, {%0,%1,%2,%3};"
        : "+f"(d[0]), "+f"(d[1]), "+f"(d[2]), "+f"(d[3])
        : "r"(a[0]), "r"(a[1]), "r"(a[2]), "r"(a[3]), "r"(b[0]), "r"(b[1]));
}
__device__ __forceinline__ uint32_t packh(float a, float b) {   // a -> low half
    uint32_t r;
    asm("cvt.rn.f16x2.f32 %0, %1, %2;" : "=r"(r) : "f"(b), "f"(a));
    return r;
}
__device__ __forceinline__ uint32_t swz(int r, int c) {
    return (uint32_t)(r * 64 + ((c ^ ((r >> 1) & 3)) << 4));
}
__device__ __forceinline__ uint32_t aswz(int r, int c) {
    return (uint32_t)(r * 256 + (((c ^ r) & 7) | (c & 8)) * 16);
}

// ---------------------------------------------------------------------------
// merged split kernel (4 float4 per thread)
// ---------------------------------------------------------------------------
#define N4X  ((B_*T_*C_)/4)
#define N4WA ((QKV_DIM*C_)/4)
#define N4WP ((C_*C_)/4)
#define N4ALL (N4X + N4WA + N4WP)
#define SPLIT_PER_THREAD 4
#define SPLIT_BLOCKS ((N4ALL + 256 * SPLIT_PER_THREAD - 1) / (256 * SPLIT_PER_THREAD))

__global__ __launch_bounds__(256) void split_all_kernel(
    const float* __restrict__ x, const float* __restrict__ wa, const float* __restrict__ wp)
{
    int base = (blockIdx.x * 256) * SPLIT_PER_THREAD + threadIdx.x;
    float4 v[SPLIT_PER_THREAD];
    int idx[SPLIT_PER_THREAD];
    int kind[SPLIT_PER_THREAD];
#pragma unroll
    for (int u = 0; u < SPLIT_PER_THREAD; u++) {
        int i = base + u * 256;
        idx[u] = i; kind[u] = 3;
        if (i < N4X)            { kind[u] = 0; v[u] = ((const float4*)x)[i]; }
        else if (i < N4X + N4WA){ kind[u] = 1; v[u] = ((const float4*)wa)[i - N4X]; }
        else if (i < N4ALL)     { kind[u] = 2; v[u] = ((const float4*)wp)[i - N4X - N4WA]; }
    }
#pragma unroll
    for (int u = 0; u < SPLIT_PER_THREAD; u++) {
        if (kind[u] == 0) {
            int i = idx[u];
            __half h0 = __float2half(v[u].x), h1 = __float2half(v[u].y);
            __half h2 = __float2half(v[u].z), h3 = __float2half(v[u].w);
            ((uint32_t*)g_xhi)[2 * i]     = packh(__half2float(h0), __half2float(h1));
            ((uint32_t*)g_xhi)[2 * i + 1] = packh(__half2float(h2), __half2float(h3));
            ((uint32_t*)g_xlo)[2 * i]     = packh(v[u].x - __half2float(h0), v[u].y - __half2float(h1));
            ((uint32_t*)g_xlo)[2 * i + 1] = packh(v[u].z - __half2float(h2), v[u].w - __half2float(h3));
        } else if (kind[u] == 1) {
            int i = idx[u] - N4X;
            ((uint32_t*)g_wahi)[2 * i]     = packh(v[u].x, v[u].y);
            ((uint32_t*)g_wahi)[2 * i + 1] = packh(v[u].z, v[u].w);
        } else if (kind[u] == 2) {
            int i = idx[u] - N4X - N4WA;
            ((uint32_t*)g_wphi)[2 * i]     = packh(v[u].x, v[u].y);
            ((uint32_t*)g_wphi)[2 * i + 1] = packh(v[u].z, v[u].w);
        }
    }
}

// ---------------------------------------------------------------------------
// fp16 GEMM (NT) via mma.sync. Per-CTA uniform lo-skip:
//   blockIdx.x <  nlo_tiles: C = (Ahi+Alo) * Bhi^T  (2-pass)
//   blockIdx.x >= nlo_tiles: C =  Ahi      * Bhi^T  (1-pass; V columns)
// Single launch so the scheduler backfills cheap CTAs into the same waves.
// ---------------------------------------------------------------------------
#define GSTAGE 24576
#define GSMEM (3 * GSTAGE)

__global__ __launch_bounds__(128, 2) void gemm_mma_kernel(
    const __half* __restrict__ Ahi, const __half* __restrict__ Alo,
    const __half* __restrict__ Bhi,
    float* __restrict__ C, int M, int N, int K, int nlo_tiles)
{
    extern __shared__ unsigned char gsm_raw[];
    uint32_t sb = smem_u32(gsm_raw);

    int tid = threadIdx.x;
    int wid = tid >> 5, lane = tid & 31;
    int wm = wid >> 1, wn = wid & 1;
    int m0 = blockIdx.y * 128, n0 = blockIdx.x * 128;
    int grp = lane >> 2, qid = lane & 3;
    const bool dolo = (int)blockIdx.x < nlo_tiles;   // uniform per CTA

    float acc[4][8][4];
#pragma unroll
    for (int mi = 0; mi < 4; mi++)
#pragma unroll
        for (int ni = 0; ni < 8; ni++)
#pragma unroll
            for (int r = 0; r < 4; r++) acc[mi][ni][r] = 0.f;

    int nch = K >> 5;

    auto issue = [&](int c) {
        int kofs = c << 5;
        int s = c % 3;
        uint32_t st = sb + s * GSTAGE;
#pragma unroll
        for (int it = 0; it < 4; it++) {
            int idx = tid + it * 128;
            int r = idx >> 2, ch = idx & 3;
            uint32_t o = swz(r, ch);
            size_t ga = (size_t)(m0 + r) * K + kofs + ch * 8;
            size_t gb = (size_t)(n0 + r) * K + kofs + ch * 8;
            cp_async16(st + o,         Ahi + ga);
            if (dolo) cp_async16(st + 8192 + o, Alo + ga);
            cp_async16(st + 16384 + o, Bhi + gb);
        }
        cp_commit();
    };

    issue(0);
    issue(1);

    int lrow_add = (lane & 7) + (((lane >> 3) & 1) << 3);
    int lchunk_add = lane >> 4;

    for (int c = 0; c < nch; c++) {
        if (c + 1 < nch) cp_wait1(); else cp_wait0();
        __syncthreads();
        if (c + 2 < nch) issue(c + 2);

        int s = c % 3;
        uint32_t aH = sb + s * GSTAGE;
        uint32_t aL = aH + 8192;
        uint32_t bH = aH + 16384;

#pragma unroll
        for (int ks = 0; ks < 2; ks++) {
            int cbase = ks * 2 + lchunk_add;
            uint32_t ahi[4][4], alo[4][4];
#pragma unroll
            for (int mi = 0; mi < 4; mi++) {
                int row = wm * 64 + mi * 16 + lrow_add;
                uint32_t o = swz(row, cbase);
                ldm_x4(ahi[mi][0], ahi[mi][1], ahi[mi][2], ahi[mi][3], aH + o);
                if (dolo) ldm_x4(alo[mi][0], alo[mi][1], alo[mi][2], alo[mi][3], aL + o);
            }
#pragma unroll
            for (int nh = 0; nh < 2; nh++) {
                uint32_t bh[4][2];
#pragma unroll
                for (int p = 0; p < 2; p++) {
                    int row = wn * 64 + nh * 32 + p * 16 + lrow_add;
                    uint32_t o = swz(row, cbase);
                    uint32_t t0, t1, t2, t3;
                    ldm_x4(t0, t1, t2, t3, bH + o);
                    bh[p * 2][0] = t0;     bh[p * 2][1] = t2;
                    bh[p * 2 + 1][0] = t1; bh[p * 2 + 1][1] = t3;
                }
                if (dolo) {
#pragma unroll
                    for (int mi = 0; mi < 4; mi++)
#pragma unroll
                        for (int ni = 0; ni < 4; ni++) {
                            float* d = acc[mi][nh * 4 + ni];
                            mma_f16(d, ahi[mi], bh[ni]);
                            mma_f16(d, alo[mi], bh[ni]);
                        }
                } else {
#pragma unroll
                    for (int mi = 0; mi < 4; mi++)
#pragma unroll
                        for (int ni = 0; ni < 4; ni++)
                            mma_f16(acc[mi][nh * 4 + ni], ahi[mi], bh[ni]);
                }
            }
        }
    }

#pragma unroll
    for (int mi = 0; mi < 4; mi++) {
        int rbase = m0 + wm * 64 + mi * 16 + grp;
#pragma unroll
        for (int ni = 0; ni < 8; ni++) {
            int col = n0 + wn * 64 + ni * 8 + qid * 2;
            float* p0 = C + (size_t)rbase * N + col;
            float* p1 = C + (size_t)(rbase + 8) * N + col;
            p0[0] = acc[mi][ni][0]; p0[1] = acc[mi][ni][1];
            p1[0] = acc[mi][ni][2]; p1[1] = acc[mi][ni][3];
        }
    }
}

// ---------------------------------------------------------------------------
// RoPE + RMSnorm -> fp16 planes. q: hi+lo (UNSCALED). k,v: hi.
// ---------------------------------------------------------------------------
__global__ __launch_bounds__(256) void rope_rms_kernel(
    const float* __restrict__ cosb, const float* __restrict__ sinb)
{
    int bt = blockIdx.x;
    int b = bt / T_, t = bt % T_;
    int warp = threadIdx.x >> 5, lane = threadIdx.x & 31;
    const float* base = g_qkv + (size_t)bt * QKV_DIM;

    float c0 = cosb[t * 64 + lane], c1 = cosb[t * 64 + lane + 32];
    float s0 = sinb[t * 64 + lane], s1 = sinb[t * 64 + lane + 32];

    for (int hh = warp; hh < NH + NKV; hh += 8) {
        const float* src;
        __half *dhi, *dlo;
        bool isq;
        if (hh < NH) {
            src = base + hh * HD;
            size_t o = ((size_t)(b * NH + hh) * T_ + t) * HD;
            dhi = g_qhi + o; dlo = g_qlo + o; isq = true;
        } else {
            int kv = hh - NH;
            src = base + C_ + kv * HD;
            size_t o = ((size_t)(b * NKV + kv) * T_ + t) * HD;
            dhi = g_khi + o; dlo = nullptr; isq = false;
        }
        float v0 = src[lane], v1 = src[lane + 32], v2 = src[lane + 64], v3 = src[lane + 96];
        float y0 =  v0 * c0 + v2 * s0;
        float y2 = -v0 * s0 + v2 * c0;
        float y1 =  v1 * c1 + v3 * s1;
        float y3 = -v1 * s1 + v3 * c1;
        float ss = y0 * y0 + y1 * y1 + y2 * y2 + y3 * y3;
#pragma unroll
        for (int o = 16; o > 0; o >>= 1) ss += __shfl_xor_sync(0xffffffffu, ss, o);
        float r = rsqrtf(ss * (1.0f / HD) + EPS_);
        float w0 = y0 * r, w1 = y1 * r, w2 = y2 * r, w3 = y3 * r;
        __half h0 = __float2half(w0), h1 = __float2half(w1);
        __half h2 = __float2half(w2), h3 = __float2half(w3);
        dhi[lane]      = h0;
        dhi[lane + 32] = h1;
        dhi[lane + 64] = h2;
        dhi[lane + 96] = h3;
        if (isq) {
            dlo[lane]      = __float2half(w0 - __half2float(h0));
            dlo[lane + 32] = __float2half(w1 - __half2float(h1));
            dlo[lane + 64] = __float2half(w2 - __half2float(h2));
            dlo[lane + 96] = __float2half(w3 - __half2float(h3));
        }
    }
    // V convert (hi only)
    {
        int kv = warp;
        const float4* src = (const float4*)(base + C_ + KVD + kv * HD);
        float4 v = src[lane];
        size_t o = ((size_t)(b * NKV + kv) * T_ + t) * HD + 4 * lane;
        *(uint32_t*)(g_vhi + o)     = packh(v.x, v.y);
        *(uint32_t*)(g_vhi + o + 2) = packh(v.z, v.w);
    }
}

// ---------------------------------------------------------------------------
// fp16 2-pass tensor-core flash attention, causal, GQA.
// qt reversed (longest CTAs first) for causal tail balancing.
// ---------------------------------------------------------------------------
#define ATT_SMEM (4 * 16384)

__global__ __launch_bounds__(128) void attn_mma_kernel()
{
    extern __shared__ unsigned char attn_smem_raw[];
    uint32_t sb = smem_u32(attn_smem_raw);
    const uint32_t QH = 0, QL = 16384, KHs = 32768, VHs = 49152;

    int qt = (int)gridDim.x - 1 - (int)blockIdx.x;   // longest first
    int h = blockIdx.y, b = blockIdx.z;
    int kvh = h >> 1;
    int tid = threadIdx.x, wid = tid >> 5, lane = tid & 31;
    int grp = lane >> 2, qid = lane & 3;
    int q0 = qt * 64;

    const __half* qh = g_qhi + ((size_t)(b * NH + h) * T_ + q0) * HD;
    const __half* ql = g_qlo + ((size_t)(b * NH + h) * T_ + q0) * HD;
    const __half* kh = g_khi + ((size_t)(b * NKV + kvh) * T_) * HD;
    const __half* vh = g_vhi + ((size_t)(b * NKV + kvh) * T_) * HD;

    for (int i = tid; i < 1024; i += 128) {
        int r = i >> 4, c = i & 15;
        uint32_t o = aswz(r, c);
        cp_async16(sb + QH + o, qh + (size_t)r * HD + c * 8);
        cp_async16(sb + QL + o, ql + (size_t)r * HD + c * 8);
    }
    cp_commit();

    float O[16][4];
#pragma unroll
    for (int t = 0; t < 16; t++)
#pragma unroll
        for (int r = 0; r < 4; r++) O[t][r] = 0.f;
    float m0 = -1e30f, m1 = -1e30f, l0 = 0.f, l1 = 0.f;

    int csel = lane >> 4;
    int arow = wid * 16 + (lane & 15);

    for (int kt = 0; kt <= qt; kt++) {
        int k0 = kt * 64;
        for (int i = tid; i < 1024; i += 128) {
            int r = i >> 4, c = i & 15;
            uint32_t o = aswz(r, c);
            cp_async16(sb + KHs + o, kh + (size_t)(k0 + r) * HD + c * 8);
        }
        cp_commit();
        for (int i = tid; i < 1024; i += 128) {
            int r = i >> 4, c = i & 15;
            uint32_t o = aswz(r, c);
            cp_async16(sb + VHs + o, vh + (size_t)(k0 + r) * HD + c * 8);
        }
        cp_commit();
        cp_wait1();
        __syncthreads();

        float s[8][4];
#pragma unroll
        for (int j = 0; j < 8; j++)
#pragma unroll
            for (int r = 0; r < 4; r++) s[j][r] = 0.f;

#pragma unroll
        for (int ks = 0; ks < 8; ks++) {
            int ch = 2 * ks + csel;
            uint32_t ah[4], al[4];
            ldm_x4(ah[0], ah[1], ah[2], ah[3], sb + QH + aswz(arow, ch));
            ldm_x4(al[0], al[1], al[2], al[3], sb + QL + aswz(arow, ch));
#pragma unroll
            for (int nt = 0; nt < 4; nt++) {
                int krow = nt * 16 + (lane & 15);
                uint32_t t0, t1, t2, t3;
                ldm_x4(t0, t1, t2, t3, sb + KHs + aswz(krow, ch));
                uint32_t bh0[2] = {t0, t2}, bh1[2] = {t1, t3};
                mma_f16(s[2 * nt], ah, bh0);     mma_f16(s[2 * nt + 1], ah, bh1);
                mma_f16(s[2 * nt], al, bh0);     mma_f16(s[2 * nt + 1], al, bh1);
            }
        }

#pragma unroll
        for (int j = 0; j < 8; j++) {
            s[j][0] *= SCALE_; s[j][1] *= SCALE_; s[j][2] *= SCALE_; s[j][3] *= SCALE_;
        }
        if (kt == qt) {
            int r0g = q0 + wid * 16 + grp;
#pragma unroll
            for (int j = 0; j < 8; j++) {
                int cb = k0 + j * 8 + 2 * qid;
                if (cb > r0g)         s[j][0] = -1e30f;
                if (cb + 1 > r0g)     s[j][1] = -1e30f;
                if (cb > r0g + 8)     s[j][2] = -1e30f;
                if (cb + 1 > r0g + 8) s[j][3] = -1e30f;
            }
        }

        float mx0 = -1e30f, mx1 = -1e30f;
#pragma unroll
        for (int j = 0; j < 8; j++) {
            mx0 = fmaxf(mx0, fmaxf(s[j][0], s[j][1]));
            mx1 = fmaxf(mx1, fmaxf(s[j][2], s[j][3]));
        }
        mx0 = fmaxf(mx0, __shfl_xor_sync(0xffffffffu, mx0, 1));
        mx0 = fmaxf(mx0, __shfl_xor_sync(0xffffffffu, mx0, 2));
        mx1 = fmaxf(mx1, __shfl_xor_sync(0xffffffffu, mx1, 1));
        mx1 = fmaxf(mx1, __shfl_xor_sync(0xffffffffu, mx1, 2));
        float nm0 = fmaxf(m0, mx0), nm1 = fmaxf(m1, mx1);
        float f0 = __expf(m0 - nm0), f1 = __expf(m1 - nm1);
        m0 = nm0; m1 = nm1;
        float sum0 = 0.f, sum1 = 0.f;
#pragma unroll
        for (int j = 0; j < 8; j++) {
            s[j][0] = __expf(s[j][0] - nm0);
            s[j][1] = __expf(s[j][1] - nm0);
            s[j][2] = __expf(s[j][2] - nm1);
            s[j][3] = __expf(s[j][3] - nm1);
            sum0 += s[j][0] + s[j][1];
            sum1 += s[j][2] + s[j][3];
        }
        sum0 += __shfl_xor_sync(0xffffffffu, sum0, 1);
        sum0 += __shfl_xor_sync(0xffffffffu, sum0, 2);
        sum1 += __shfl_xor_sync(0xffffffffu, sum1, 1);
        sum1 += __shfl_xor_sync(0xffffffffu, sum1, 2);
        l0 = l0 * f0 + sum0;
        l1 = l1 * f1 + sum1;
#pragma unroll
        for (int t = 0; t < 16; t++) {
            O[t][0] *= f0; O[t][1] *= f0; O[t][2] *= f1; O[t][3] *= f1;
        }

        cp_wait0();
        __syncthreads();

#pragma unroll
        for (int kc = 0; kc < 4; kc++) {
            float p00 = s[2 * kc][0], p01 = s[2 * kc][1], p02 = s[2 * kc][2], p03 = s[2 * kc][3];
            float p10 = s[2 * kc + 1][0], p11 = s[2 * kc + 1][1], p12 = s[2 * kc + 1][2], p13 = s[2 * kc + 1][3];
            uint32_t ph[4], pl[4];
            ph[0] = packh(p00, p01); ph[1] = packh(p02, p03);
            ph[2] = packh(p10, p11); ph[3] = packh(p12, p13);
            float q00 = p00 - __half2float(__float2half(p00));
            float q01 = p01 - __half2float(__float2half(p01));
            float q02 = p02 - __half2float(__float2half(p02));
            float q03 = p03 - __half2float(__float2half(p03));
            float q10 = p10 - __half2float(__float2half(p10));
            float q11 = p11 - __half2float(__float2half(p11));
            float q12 = p12 - __half2float(__float2half(p12));
            float q13 = p13 - __half2float(__float2half(p13));
            pl[0] = packh(q00, q01); pl[1] = packh(q02, q03);
            pl[2] = packh(q10, q11); pl[3] = packh(q12, q13);

            int vrow = kc * 16 + ((lane >> 3) & 1) * 8 + (lane & 7);
#pragma unroll
            for (int dn = 0; dn < 8; dn++) {
                int ch2 = 2 * dn + csel;
                uint32_t t0, t1, t2, t3;
                ldmt_x4(t0, t1, t2, t3, sb + VHs + aswz(vrow, ch2));
                uint32_t bh0[2] = {t0, t1}, bh1[2] = {t2, t3};
                mma_f16(O[2 * dn], ph, bh0);     mma_f16(O[2 * dn + 1], ph, bh1);
                mma_f16(O[2 * dn], pl, bh0);     mma_f16(O[2 * dn + 1], pl, bh1);
            }
        }
        __syncthreads();
    }

    float i0 = 1.0f / l0, i1 = 1.0f / l1;
    int r0g = q0 + wid * 16 + grp;
    size_t base0 = ((size_t)(b * T_) + r0g) * C_ + h * HD;
    size_t base1 = base0 + (size_t)8 * C_;
#pragma unroll
    for (int t = 0; t < 16; t++) {
        int col = t * 8 + 2 * qid;
        float v0 = O[t][0] * i0, v1 = O[t][1] * i0;
        float v2 = O[t][2] * i1, v3 = O[t][3] * i1;
        float h0 = __half2float(__float2half(v0));
        float h1 = __half2float(__float2half(v1));
        float h2 = __half2float(__float2half(v2));
        float h3 = __half2float(__float2half(v3));
        *(uint32_t*)(g_yhi + base0 + col) = packh(v0, v1);
        *(uint32_t*)(g_ylo + base0 + col) = packh(v0 - h0, v1 - h1);
        *(uint32_t*)(g_yhi + base1 + col) = packh(v2, v3);
        *(uint32_t*)(g_ylo + base1 + col) = packh(v2 - h2, v3 - h3);
    }
}

// ---------------------------------------------------------------------------
// Launch pipeline
// ---------------------------------------------------------------------------
extern "C" void kernel_launch(void* const* d_in, const int* in_sizes, int n_in,
                              void* d_out, int out_size)
{
    const float* x      = (const float*)d_in[0];
    const float* w_attn = (const float*)d_in[1];
    const float* w_proj = (const float*)d_in[2];
    const float* cosb   = (const float*)d_in[3];
    const float* sinb   = (const float*)d_in[4];
    float* out = (float*)d_out;

    void *p_qkv, *p_xhi, *p_xlo, *p_wahi, *p_wphi, *p_yhi, *p_ylo;
    cudaGetSymbolAddress(&p_qkv, g_qkv);
    cudaGetSymbolAddress(&p_xhi, g_xhi);  cudaGetSymbolAddress(&p_xlo, g_xlo);
    cudaGetSymbolAddress(&p_wahi, g_wahi);
    cudaGetSymbolAddress(&p_wphi, g_wphi);
    cudaGetSymbolAddress(&p_yhi, g_yhi);  cudaGetSymbolAddress(&p_ylo, g_ylo);

    cudaFuncSetAttribute(attn_mma_kernel, cudaFuncAttributeMaxDynamicSharedMemorySize, ATT_SMEM);
    cudaFuncSetAttribute(gemm_mma_kernel, cudaFuncAttributeMaxDynamicSharedMemorySize, GSMEM);

    split_all_kernel<<<SPLIT_BLOCKS, 256>>>(x, w_attn, w_proj);

    // QKV GEMM: single launch; CTAs 0..23 (q/k cols) do lo correction, 24..31 (v cols) hi-only
    dim3 g1(QKV_DIM / 128, (B_ * T_) / 128);
    gemm_mma_kernel<<<g1, 128, GSMEM>>>(
        (const __half*)p_xhi, (const __half*)p_xlo, (const __half*)p_wahi,
        (float*)p_qkv, B_ * T_, QKV_DIM, C_, 24);

    rope_rms_kernel<<<B_ * T_, 256>>>(cosb, sinb);

    dim3 ga(T_ / 64, NH, B_);
    attn_mma_kernel<<<ga, 128, ATT_SMEM>>>();

    dim3 g2(C_ / 128, (B_ * T_) / 128);
    gemm_mma_kernel<<<g2, 128, GSMEM>>>(
        (const __half*)p_yhi, (const __half*)p_ylo, (const __half*)p_wphi,
        out, B_ * T_, C_, C_, 16);
}

// round 17
// speedup vs baseline: 1.0211x; 1.0211x over previous
#include <cuda_runtime.h>
#include <cuda_bf16.h>
#include <cuda_fp16.h>
#include <cstdint>
#include <math.h>

// Problem constants
#define B_   2
#define T_   2048
#define C_   2048
#define NH   16
#define NKV  8
#define HD   128
#define KVD  (NKV*HD)          // 1024
#define QKV_DIM (C_ + 2*KVD)   // 4096
#define EPS_ 1.1920929e-07f
#define SCALE_ 0.08838834764831845f   // 1/sqrt(128)

// ---------------- scratch (static device globals; allocation-free) ----------
__device__ float g_qkv[(size_t)B_*T_*QKV_DIM];   // 64 MB
__device__ __half g_xhi[(size_t)B_*T_*C_];
__device__ __half g_xlo[(size_t)B_*T_*C_];
__device__ __half g_wahi[(size_t)QKV_DIM*C_];
__device__ __half g_wphi[(size_t)C_*C_];
__device__ __half g_yhi[(size_t)B_*T_*C_];
__device__ __half g_ylo[(size_t)B_*T_*C_];
__device__ __half g_qhi[(size_t)B_*NH*T_*HD];
__device__ __half g_qlo[(size_t)B_*NH*T_*HD];
__device__ __half g_khi[(size_t)B_*NKV*T_*HD];
__device__ __half g_vhi[(size_t)B_*NKV*T_*HD];

// ---------------------------------------------------------------------------
// helpers
// ---------------------------------------------------------------------------
__device__ __forceinline__ uint32_t smem_u32(const void* p) {
    uint32_t a;
    asm("{ .reg .u64 t; cvta.to.shared.u64 t, %1; cvt.u32.u64 %0, t; }" : "=r"(a) : "l"(p));
    return a;
}
__device__ __forceinline__ void cp_async16(uint32_t dst, const void* src) {
    asm volatile("cp.async.cg.shared.global [%0], [%1], 16;" :: "r"(dst), "l"(src));
}
__device__ __forceinline__ void cp_commit() { asm volatile("cp.async.commit_group;"); }
__device__ __forceinline__ void cp_wait2() { asm volatile("cp.async.wait_group 2;"); }
__device__ __forceinline__ void cp_wait1() { asm volatile("cp.async.wait_group 1;"); }
__device__ __forceinline__ void cp_wait0() { asm volatile("cp.async.wait_group 0;"); }
__device__ __forceinline__ void ldm_x4(uint32_t& r0, uint32_t& r1, uint32_t& r2, uint32_t& r3, uint32_t a) {
    asm volatile("ldmatrix.sync.aligned.m8n8.x4.shared.b16 {%0,%1,%2,%3}, [%4];"
                 : "=r"(r0), "=r"(r1), "=r"(r2), "=r"(r3) : "r"(a));
}
__device__ __forceinline__ void ldmt_x4(uint32_t& r0, uint32_t& r1, uint32_t& r2, uint32_t& r3, uint32_t a) {
    asm volatile("ldmatrix.sync.aligned.m8n8.x4.trans.shared.b16 {%0,%1,%2,%3}, [%4];"
                 : "=r"(r0), "=r"(r1), "=r"(r2), "=r"(r3) : "r"(a));
}
__device__ __forceinline__ void mma_f16(float* d, const uint32_t* a, const uint32_t* b) {
    asm volatile(
        "mma.sync.aligned.m16n8k16.row.col.f32.f16.f16.f32 "
        "{%0,%1,%2,%3}, {%4,%5,%6,%7}, {%8,%9}, {%0,%1,%2,%3};"
        : "+f"(d[0]), "+f"(d[1]), "+f"(d[2]), "+f"(d[3])
        : "r"(a[0]), "r"(a[1]), "r"(a[2]), "r"(a[3]), "r"(b[0]), "r"(b[1]));
}
__device__ __forceinline__ uint32_t packh(float a, float b) {   // a -> low half
    uint32_t r;
    asm("cvt.rn.f16x2.f32 %0, %1, %2;" : "=r"(r) : "f"(b), "f"(a));
    return r;
}
__device__ __forceinline__ uint32_t swz(int r, int c) {
    return (uint32_t)(r * 64 + ((c ^ ((r >> 1) & 3)) << 4));
}
__device__ __forceinline__ uint32_t aswz(int r, int c) {
    return (uint32_t)(r * 256 + (((c ^ r) & 7) | (c & 8)) * 16);
}

// ---------------------------------------------------------------------------
// merged split kernel (4 float4 per thread)
// ---------------------------------------------------------------------------
#define N4X  ((B_*T_*C_)/4)
#define N4WA ((QKV_DIM*C_)/4)
#define N4WP ((C_*C_)/4)
#define N4ALL (N4X + N4WA + N4WP)
#define SPLIT_PER_THREAD 4
#define SPLIT_BLOCKS ((N4ALL + 256 * SPLIT_PER_THREAD - 1) / (256 * SPLIT_PER_THREAD))

__global__ __launch_bounds__(256) void split_all_kernel(
    const float* __restrict__ x, const float* __restrict__ wa, const float* __restrict__ wp)
{
    int base = (blockIdx.x * 256) * SPLIT_PER_THREAD + threadIdx.x;
    float4 v[SPLIT_PER_THREAD];
    int idx[SPLIT_PER_THREAD];
    int kind[SPLIT_PER_THREAD];
#pragma unroll
    for (int u = 0; u < SPLIT_PER_THREAD; u++) {
        int i = base + u * 256;
        idx[u] = i; kind[u] = 3;
        if (i < N4X)            { kind[u] = 0; v[u] = ((const float4*)x)[i]; }
        else if (i < N4X + N4WA){ kind[u] = 1; v[u] = ((const float4*)wa)[i - N4X]; }
        else if (i < N4ALL)     { kind[u] = 2; v[u] = ((const float4*)wp)[i - N4X - N4WA]; }
    }
#pragma unroll
    for (int u = 0; u < SPLIT_PER_THREAD; u++) {
        if (kind[u] == 0) {
            int i = idx[u];
            __half h0 = __float2half(v[u].x), h1 = __float2half(v[u].y);
            __half h2 = __float2half(v[u].z), h3 = __float2half(v[u].w);
            ((uint32_t*)g_xhi)[2 * i]     = packh(__half2float(h0), __half2float(h1));
            ((uint32_t*)g_xhi)[2 * i + 1] = packh(__half2float(h2), __half2float(h3));
            ((uint32_t*)g_xlo)[2 * i]     = packh(v[u].x - __half2float(h0), v[u].y - __half2float(h1));
            ((uint32_t*)g_xlo)[2 * i + 1] = packh(v[u].z - __half2float(h2), v[u].w - __half2float(h3));
        } else if (kind[u] == 1) {
            int i = idx[u] - N4X;
            ((uint32_t*)g_wahi)[2 * i]     = packh(v[u].x, v[u].y);
            ((uint32_t*)g_wahi)[2 * i + 1] = packh(v[u].z, v[u].w);
        } else if (kind[u] == 2) {
            int i = idx[u] - N4X - N4WA;
            ((uint32_t*)g_wphi)[2 * i]     = packh(v[u].x, v[u].y);
            ((uint32_t*)g_wphi)[2 * i + 1] = packh(v[u].z, v[u].w);
        }
    }
}

// ---------------------------------------------------------------------------
// fp16 2-pass GEMM (NT) via mma.sync: C = (Ahi+Alo) * Bhi^T, fp32 acc.
// 4-stage cp.async pipeline (96KB dynamic smem), one barrier per chunk.
// ---------------------------------------------------------------------------
#define GSTAGE 24576
#define GNST 4
#define GSMEM (GNST * GSTAGE)

__global__ __launch_bounds__(128, 2) void gemm_mma_kernel(
    const __half* __restrict__ Ahi, const __half* __restrict__ Alo,
    const __half* __restrict__ Bhi,
    float* __restrict__ C, int M, int N, int K)
{
    extern __shared__ unsigned char gsm_raw[];
    uint32_t sb = smem_u32(gsm_raw);

    int tid = threadIdx.x;
    int wid = tid >> 5, lane = tid & 31;
    int wm = wid >> 1, wn = wid & 1;      // warp grid 2x2
    int m0 = blockIdx.y * 128, n0 = blockIdx.x * 128;
    int grp = lane >> 2, qid = lane & 3;

    float acc[4][8][4];
#pragma unroll
    for (int mi = 0; mi < 4; mi++)
#pragma unroll
        for (int ni = 0; ni < 8; ni++)
#pragma unroll
            for (int r = 0; r < 4; r++) acc[mi][ni][r] = 0.f;

    int nch = K >> 5;

    auto issue = [&](int c) {
        int kofs = c << 5;
        int s = c & 3;                 // 4 stages
        uint32_t st = sb + s * GSTAGE;
#pragma unroll
        for (int it = 0; it < 4; it++) {
            int idx = tid + it * 128;
            int r = idx >> 2, ch = idx & 3;
            uint32_t o = swz(r, ch);
            size_t ga = (size_t)(m0 + r) * K + kofs + ch * 8;
            size_t gb = (size_t)(n0 + r) * K + kofs + ch * 8;
            cp_async16(st + o,         Ahi + ga);
            cp_async16(st + 8192 + o,  Alo + ga);
            cp_async16(st + 16384 + o, Bhi + gb);
        }
        cp_commit();
    };

    issue(0);
    issue(1);
    issue(2);

    int lrow_add = (lane & 7) + (((lane >> 3) & 1) << 3);
    int lchunk_add = lane >> 4;

    for (int c = 0; c < nch; c++) {
        int pend = nch - 1 - c;
        if (pend >= 2) cp_wait2();
        else if (pend == 1) cp_wait1();
        else cp_wait0();
        __syncthreads();
        if (c + 3 < nch) issue(c + 3);

        int s = c & 3;
        uint32_t aH = sb + s * GSTAGE;
        uint32_t aL = aH + 8192;
        uint32_t bH = aH + 16384;

#pragma unroll
        for (int ks = 0; ks < 2; ks++) {
            int cbase = ks * 2 + lchunk_add;
            uint32_t ahi[4][4], alo[4][4];
#pragma unroll
            for (int mi = 0; mi < 4; mi++) {
                int row = wm * 64 + mi * 16 + lrow_add;
                uint32_t o = swz(row, cbase);
                ldm_x4(ahi[mi][0], ahi[mi][1], ahi[mi][2], ahi[mi][3], aH + o);
                ldm_x4(alo[mi][0], alo[mi][1], alo[mi][2], alo[mi][3], aL + o);
            }
#pragma unroll
            for (int nh = 0; nh < 2; nh++) {
                uint32_t bh[4][2];
#pragma unroll
                for (int p = 0; p < 2; p++) {
                    int row = wn * 64 + nh * 32 + p * 16 + lrow_add;
                    uint32_t o = swz(row, cbase);
                    uint32_t t0, t1, t2, t3;
                    ldm_x4(t0, t1, t2, t3, bH + o);
                    bh[p * 2][0] = t0;     bh[p * 2][1] = t2;
                    bh[p * 2 + 1][0] = t1; bh[p * 2 + 1][1] = t3;
                }
#pragma unroll
                for (int mi = 0; mi < 4; mi++)
#pragma unroll
                    for (int ni = 0; ni < 4; ni++) {
                        float* d = acc[mi][nh * 4 + ni];
                        mma_f16(d, ahi[mi], bh[ni]);
                        mma_f16(d, alo[mi], bh[ni]);
                    }
            }
        }
    }

#pragma unroll
    for (int mi = 0; mi < 4; mi++) {
        int rbase = m0 + wm * 64 + mi * 16 + grp;
#pragma unroll
        for (int ni = 0; ni < 8; ni++) {
            int col = n0 + wn * 64 + ni * 8 + qid * 2;
            float* p0 = C + (size_t)rbase * N + col;
            float* p1 = C + (size_t)(rbase + 8) * N + col;
            p0[0] = acc[mi][ni][0]; p0[1] = acc[mi][ni][1];
            p1[0] = acc[mi][ni][2]; p1[1] = acc[mi][ni][3];
        }
    }
}

// ---------------------------------------------------------------------------
// RoPE + RMSnorm -> fp16 planes. q: hi+lo (UNSCALED). k,v: hi.
// ---------------------------------------------------------------------------
__global__ __launch_bounds__(256) void rope_rms_kernel(
    const float* __restrict__ cosb, const float* __restrict__ sinb)
{
    int bt = blockIdx.x;
    int b = bt / T_, t = bt % T_;
    int warp = threadIdx.x >> 5, lane = threadIdx.x & 31;
    const float* base = g_qkv + (size_t)bt * QKV_DIM;

    float c0 = cosb[t * 64 + lane], c1 = cosb[t * 64 + lane + 32];
    float s0 = sinb[t * 64 + lane], s1 = sinb[t * 64 + lane + 32];

    for (int hh = warp; hh < NH + NKV; hh += 8) {
        const float* src;
        __half *dhi, *dlo;
        bool isq;
        if (hh < NH) {
            src = base + hh * HD;
            size_t o = ((size_t)(b * NH + hh) * T_ + t) * HD;
            dhi = g_qhi + o; dlo = g_qlo + o; isq = true;
        } else {
            int kv = hh - NH;
            src = base + C_ + kv * HD;
            size_t o = ((size_t)(b * NKV + kv) * T_ + t) * HD;
            dhi = g_khi + o; dlo = nullptr; isq = false;
        }
        float v0 = src[lane], v1 = src[lane + 32], v2 = src[lane + 64], v3 = src[lane + 96];
        float y0 =  v0 * c0 + v2 * s0;
        float y2 = -v0 * s0 + v2 * c0;
        float y1 =  v1 * c1 + v3 * s1;
        float y3 = -v1 * s1 + v3 * c1;
        float ss = y0 * y0 + y1 * y1 + y2 * y2 + y3 * y3;
#pragma unroll
        for (int o = 16; o > 0; o >>= 1) ss += __shfl_xor_sync(0xffffffffu, ss, o);
        float r = rsqrtf(ss * (1.0f / HD) + EPS_);
        float w0 = y0 * r, w1 = y1 * r, w2 = y2 * r, w3 = y3 * r;
        __half h0 = __float2half(w0), h1 = __float2half(w1);
        __half h2 = __float2half(w2), h3 = __float2half(w3);
        dhi[lane]      = h0;
        dhi[lane + 32] = h1;
        dhi[lane + 64] = h2;
        dhi[lane + 96] = h3;
        if (isq) {
            dlo[lane]      = __float2half(w0 - __half2float(h0));
            dlo[lane + 32] = __float2half(w1 - __half2float(h1));
            dlo[lane + 64] = __float2half(w2 - __half2float(h2));
            dlo[lane + 96] = __float2half(w3 - __half2float(h3));
        }
    }
    // V convert (hi only)
    {
        int kv = warp;
        const float4* src = (const float4*)(base + C_ + KVD + kv * HD);
        float4 v = src[lane];
        size_t o = ((size_t)(b * NKV + kv) * T_ + t) * HD + 4 * lane;
        *(uint32_t*)(g_vhi + o)     = packh(v.x, v.y);
        *(uint32_t*)(g_vhi + o + 2) = packh(v.z, v.w);
    }
}

// ---------------------------------------------------------------------------
// fp16 2-pass tensor-core flash attention, causal, GQA (R14 version).
// ---------------------------------------------------------------------------
#define ATT_SMEM (4 * 16384)

__global__ __launch_bounds__(128) void attn_mma_kernel()
{
    extern __shared__ unsigned char attn_smem_raw[];
    uint32_t sb = smem_u32(attn_smem_raw);
    const uint32_t QH = 0, QL = 16384, KHs = 32768, VHs = 49152;

    int qt = blockIdx.x, h = blockIdx.y, b = blockIdx.z;
    int kvh = h >> 1;
    int tid = threadIdx.x, wid = tid >> 5, lane = tid & 31;
    int grp = lane >> 2, qid = lane & 3;
    int q0 = qt * 64;

    const __half* qh = g_qhi + ((size_t)(b * NH + h) * T_ + q0) * HD;
    const __half* ql = g_qlo + ((size_t)(b * NH + h) * T_ + q0) * HD;
    const __half* kh = g_khi + ((size_t)(b * NKV + kvh) * T_) * HD;
    const __half* vh = g_vhi + ((size_t)(b * NKV + kvh) * T_) * HD;

    for (int i = tid; i < 1024; i += 128) {
        int r = i >> 4, c = i & 15;
        uint32_t o = aswz(r, c);
        cp_async16(sb + QH + o, qh + (size_t)r * HD + c * 8);
        cp_async16(sb + QL + o, ql + (size_t)r * HD + c * 8);
    }
    cp_commit();

    float O[16][4];
#pragma unroll
    for (int t = 0; t < 16; t++)
#pragma unroll
        for (int r = 0; r < 4; r++) O[t][r] = 0.f;
    float m0 = -1e30f, m1 = -1e30f, l0 = 0.f, l1 = 0.f;

    int csel = lane >> 4;
    int arow = wid * 16 + (lane & 15);

    for (int kt = 0; kt <= qt; kt++) {
        int k0 = kt * 64;
        for (int i = tid; i < 1024; i += 128) {
            int r = i >> 4, c = i & 15;
            uint32_t o = aswz(r, c);
            cp_async16(sb + KHs + o, kh + (size_t)(k0 + r) * HD + c * 8);
        }
        cp_commit();
        for (int i = tid; i < 1024; i += 128) {
            int r = i >> 4, c = i & 15;
            uint32_t o = aswz(r, c);
            cp_async16(sb + VHs + o, vh + (size_t)(k0 + r) * HD + c * 8);
        }
        cp_commit();
        cp_wait1();
        __syncthreads();

        float s[8][4];
#pragma unroll
        for (int j = 0; j < 8; j++)
#pragma unroll
            for (int r = 0; r < 4; r++) s[j][r] = 0.f;

#pragma unroll
        for (int ks = 0; ks < 8; ks++) {
            int ch = 2 * ks + csel;
            uint32_t ah[4], al[4];
            ldm_x4(ah[0], ah[1], ah[2], ah[3], sb + QH + aswz(arow, ch));
            ldm_x4(al[0], al[1], al[2], al[3], sb + QL + aswz(arow, ch));
#pragma unroll
            for (int nt = 0; nt < 4; nt++) {
                int krow = nt * 16 + (lane & 15);
                uint32_t t0, t1, t2, t3;
                ldm_x4(t0, t1, t2, t3, sb + KHs + aswz(krow, ch));
                uint32_t bh0[2] = {t0, t2}, bh1[2] = {t1, t3};
                mma_f16(s[2 * nt], ah, bh0);     mma_f16(s[2 * nt + 1], ah, bh1);
                mma_f16(s[2 * nt], al, bh0);     mma_f16(s[2 * nt + 1], al, bh1);
            }
        }

#pragma unroll
        for (int j = 0; j < 8; j++) {
            s[j][0] *= SCALE_; s[j][1] *= SCALE_; s[j][2] *= SCALE_; s[j][3] *= SCALE_;
        }
        if (kt == qt) {
            int r0g = q0 + wid * 16 + grp;
#pragma unroll
            for (int j = 0; j < 8; j++) {
                int cb = k0 + j * 8 + 2 * qid;
                if (cb > r0g)         s[j][0] = -1e30f;
                if (cb + 1 > r0g)     s[j][1] = -1e30f;
                if (cb > r0g + 8)     s[j][2] = -1e30f;
                if (cb + 1 > r0g + 8) s[j][3] = -1e30f;
            }
        }

        float mx0 = -1e30f, mx1 = -1e30f;
#pragma unroll
        for (int j = 0; j < 8; j++) {
            mx0 = fmaxf(mx0, fmaxf(s[j][0], s[j][1]));
            mx1 = fmaxf(mx1, fmaxf(s[j][2], s[j][3]));
        }
        mx0 = fmaxf(mx0, __shfl_xor_sync(0xffffffffu, mx0, 1));
        mx0 = fmaxf(mx0, __shfl_xor_sync(0xffffffffu, mx0, 2));
        mx1 = fmaxf(mx1, __shfl_xor_sync(0xffffffffu, mx1, 1));
        mx1 = fmaxf(mx1, __shfl_xor_sync(0xffffffffu, mx1, 2));
        float nm0 = fmaxf(m0, mx0), nm1 = fmaxf(m1, mx1);
        float f0 = __expf(m0 - nm0), f1 = __expf(m1 - nm1);
        m0 = nm0; m1 = nm1;
        float sum0 = 0.f, sum1 = 0.f;
#pragma unroll
        for (int j = 0; j < 8; j++) {
            s[j][0] = __expf(s[j][0] - nm0);
            s[j][1] = __expf(s[j][1] - nm0);
            s[j][2] = __expf(s[j][2] - nm1);
            s[j][3] = __expf(s[j][3] - nm1);
            sum0 += s[j][0] + s[j][1];
            sum1 += s[j][2] + s[j][3];
        }
        sum0 += __shfl_xor_sync(0xffffffffu, sum0, 1);
        sum0 += __shfl_xor_sync(0xffffffffu, sum0, 2);
        sum1 += __shfl_xor_sync(0xffffffffu, sum1, 1);
        sum1 += __shfl_xor_sync(0xffffffffu, sum1, 2);
        l0 = l0 * f0 + sum0;
        l1 = l1 * f1 + sum1;
#pragma unroll
        for (int t = 0; t < 16; t++) {
            O[t][0] *= f0; O[t][1] *= f0; O[t][2] *= f1; O[t][3] *= f1;
        }

        cp_wait0();
        __syncthreads();

#pragma unroll
        for (int kc = 0; kc < 4; kc++) {
            float p00 = s[2 * kc][0], p01 = s[2 * kc][1], p02 = s[2 * kc][2], p03 = s[2 * kc][3];
            float p10 = s[2 * kc + 1][0], p11 = s[2 * kc + 1][1], p12 = s[2 * kc + 1][2], p13 = s[2 * kc + 1][3];
            uint32_t ph[4], pl[4];
            ph[0] = packh(p00, p01); ph[1] = packh(p02, p03);
            ph[2] = packh(p10, p11); ph[3] = packh(p12, p13);
            float q00 = p00 - __half2float(__float2half(p00));
            float q01 = p01 - __half2float(__float2half(p01));
            float q02 = p02 - __half2float(__float2half(p02));
            float q03 = p03 - __half2float(__float2half(p03));
            float q10 = p10 - __half2float(__float2half(p10));
            float q11 = p11 - __half2float(__float2half(p11));
            float q12 = p12 - __half2float(__float2half(p12));
            float q13 = p13 - __half2float(__float2half(p13));
            pl[0] = packh(q00, q01); pl[1] = packh(q02, q03);
            pl[2] = packh(q10, q11); pl[3] = packh(q12, q13);

            int vrow = kc * 16 + ((lane >> 3) & 1) * 8 + (lane & 7);
#pragma unroll
            for (int dn = 0; dn < 8; dn++) {
                int ch2 = 2 * dn + csel;
                uint32_t t0, t1, t2, t3;
                ldmt_x4(t0, t1, t2, t3, sb + VHs + aswz(vrow, ch2));
                uint32_t bh0[2] = {t0, t1}, bh1[2] = {t2, t3};
                mma_f16(O[2 * dn], ph, bh0);     mma_f16(O[2 * dn + 1], ph, bh1);
                mma_f16(O[2 * dn], pl, bh0);     mma_f16(O[2 * dn + 1], pl, bh1);
            }
        }
        __syncthreads();
    }

    float i0 = 1.0f / l0, i1 = 1.0f / l1;
    int r0g = q0 + wid * 16 + grp;
    size_t base0 = ((size_t)(b * T_) + r0g) * C_ + h * HD;
    size_t base1 = base0 + (size_t)8 * C_;
#pragma unroll
    for (int t = 0; t < 16; t++) {
        int col = t * 8 + 2 * qid;
        float v0 = O[t][0] * i0, v1 = O[t][1] * i0;
        float v2 = O[t][2] * i1, v3 = O[t][3] * i1;
        float h0 = __half2float(__float2half(v0));
        float h1 = __half2float(__float2half(v1));
        float h2 = __half2float(__float2half(v2));
        float h3 = __half2float(__float2half(v3));
        *(uint32_t*)(g_yhi + base0 + col) = packh(v0, v1);
        *(uint32_t*)(g_ylo + base0 + col) = packh(v0 - h0, v1 - h1);
        *(uint32_t*)(g_yhi + base1 + col) = packh(v2, v3);
        *(uint32_t*)(g_ylo + base1 + col) = packh(v2 - h2, v3 - h3);
    }
}

// ---------------------------------------------------------------------------
// Launch pipeline
// ---------------------------------------------------------------------------
extern "C" void kernel_launch(void* const* d_in, const int* in_sizes, int n_in,
                              void* d_out, int out_size)
{
    const float* x      = (const float*)d_in[0];
    const float* w_attn = (const float*)d_in[1];
    const float* w_proj = (const float*)d_in[2];
    const float* cosb   = (const float*)d_in[3];
    const float* sinb   = (const float*)d_in[4];
    float* out = (float*)d_out;

    void *p_qkv, *p_xhi, *p_xlo, *p_wahi, *p_wphi, *p_yhi, *p_ylo;
    cudaGetSymbolAddress(&p_qkv, g_qkv);
    cudaGetSymbolAddress(&p_xhi, g_xhi);  cudaGetSymbolAddress(&p_xlo, g_xlo);
    cudaGetSymbolAddress(&p_wahi, g_wahi);
    cudaGetSymbolAddress(&p_wphi, g_wphi);
    cudaGetSymbolAddress(&p_yhi, g_yhi);  cudaGetSymbolAddress(&p_ylo, g_ylo);

    cudaFuncSetAttribute(attn_mma_kernel, cudaFuncAttributeMaxDynamicSharedMemorySize, ATT_SMEM);
    cudaFuncSetAttribute(gemm_mma_kernel, cudaFuncAttributeMaxDynamicSharedMemorySize, GSMEM);

    split_all_kernel<<<SPLIT_BLOCKS, 256>>>(x, w_attn, w_proj);

    dim3 g1(QKV_DIM / 128, (B_ * T_) / 128);
    gemm_mma_kernel<<<g1, 128, GSMEM>>>(
        (const __half*)p_xhi, (const __half*)p_xlo, (const __half*)p_wahi,
        (float*)p_qkv, B_ * T_, QKV_DIM, C_);

    rope_rms_kernel<<<B_ * T_, 256>>>(cosb, sinb);

    dim3 ga(T_ / 64, NH, B_);
    attn_mma_kernel<<<ga, 128, ATT_SMEM>>>();

    dim3 g2(C_ / 128, (B_ * T_) / 128);
    gemm_mma_kernel<<<g2, 128, GSMEM>>>(
        (const __half*)p_yhi, (const __half*)p_ylo, (const __half*)p_wphi,
        out, B_ * T_, C_, C_);
}